// round 5
// baseline (speedup 1.0000x reference)
#include <cuda_runtime.h>
#include <cuda_bf16.h>
#include <cstdint>
#include <cstddef>

// SRNN_multi: 2-layer spiking RNN, N=512, T=1000, H=128, DOUT=20.
//   pre1[n,t,:] = x[n,t,:] @ Wi1^T + bi1 + bh1            (kernel 1, time-parallel GEMM)
//   per t:  s1 = [pre1_t + s1@Wh1^T >= 1]
//           s2 = [s1@Wi2^T + bi2 + bh2 + s2@Wh2^T >= 1]   (kernel 2, warp-per-row)
//   out = bo + (sum_t s2) @ Wo^T / T                      (telescoped epilogue)

#define NB   512
#define TS   1000
#define HD   128
#define DOUT 20
#define MTOT (NB * TS)          // 512000 flattened (n,t) rows

typedef unsigned long long ull;

// pre1 scratch, permuted: g_pre1[row*128 + lane*4 + q] = pre1[row][lane + 32*q]
__device__ float g_pre1[(size_t)MTOT * HD];

__device__ __forceinline__ ull pk2(float lo, float hi) {
    ull r; asm("mov.b64 %0, {%1, %2};" : "=l"(r) : "f"(lo), "f"(hi)); return r;
}
__device__ __forceinline__ float2 upk2(ull v) {
    float2 r; asm("mov.b64 {%0, %1}, %2;" : "=f"(r.x), "=f"(r.y) : "l"(v)); return r;
}
__device__ __forceinline__ void fma2(ull& d, ull a, ull b) {
    asm("fma.rn.f32x2 %0, %1, %2, %0;" : "+l"(d) : "l"(a), "l"(b));
}
__device__ __forceinline__ void add2(ull& d, ull a) {
    asm("add.rn.f32x2 %0, %1, %0;" : "+l"(d) : "l"(a));
}

// ---------------------------------------------------------------------------
// Kernel 1: pre1 = x @ Wi1^T + (bi1+bh1), fp32, packed-pair FMA, permuted out.
// 8000 CTAs x 256 thr; CTA tile = 64 rows; warp = 8 rows x 128 cols;
// lane owns cols {lane, lane+32, lane+64, lane+96} as two f32x2 accumulators.
// ---------------------------------------------------------------------------
__global__ void __launch_bounds__(256, 2) k1_gemm(
    const float* __restrict__ x, const float* __restrict__ Wi1,
    const float* __restrict__ bi1, const float* __restrict__ bh1)
{
    extern __shared__ float sm[];
    float* ws = sm;           // 16384 floats: ws[k*128 + (j&31)*4 + (j>>5)] = Wi1[j*128+k]
    float* xs = sm + 16384;   // 8192 floats:  xs[r*128 + k], r local in [0,64)

    const int tid = threadIdx.x, lane = tid & 31, warp = tid >> 5;

    // stage permuted Wi1
    for (int i = tid; i < HD * HD; i += 256) {
        int j = i >> 7, k = i & 127;
        ws[k * 128 + ((j & 31) << 2) + (j >> 5)] = Wi1[i];
    }
    // stage x tile (64 rows x 128)
    {
        const float4* xg = (const float4*)x + (size_t)blockIdx.x * 2048;
        float4* xs4 = (float4*)xs;
        for (int i = tid; i < 2048; i += 256) xs4[i] = xg[i];
    }
    __syncthreads();

    // bias packed per column-pair
    const ull b01 = pk2(bi1[lane]      + bh1[lane],      bi1[lane + 32] + bh1[lane + 32]);
    const ull b23 = pk2(bi1[lane + 64] + bh1[lane + 64], bi1[lane + 96] + bh1[lane + 96]);

    ull a01[8], a23[8];
#pragma unroll
    for (int i = 0; i < 8; ++i) { a01[i] = b01; a23[i] = b23; }

    const ulonglong2* W = (const ulonglong2*)ws;
    const float* xr = xs + warp * 8 * 128;

#pragma unroll 4
    for (int k = 0; k < 128; ++k) {
        const ulonglong2 w = W[k * 32 + lane];   // cols (lane,lane+32),(lane+64,lane+96)
#pragma unroll
        for (int i = 0; i < 8; ++i) {
            const float xv = xr[i * 128 + k];    // warp-uniform broadcast
            const ull xp = pk2(xv, xv);
            fma2(a01[i], xp, w.x);
            fma2(a23[i], xp, w.y);
        }
    }

    const size_t rbase = (size_t)blockIdx.x * 64 + warp * 8;
#pragma unroll
    for (int i = 0; i < 8; ++i) {
        ulonglong2 o; o.x = a01[i]; o.y = a23[i];   // == float4 {q0,q1,q2,q3}
        *(ulonglong2*)(g_pre1 + (rbase + i) * 128 + lane * 4) = o;
    }
}

// ---------------------------------------------------------------------------
// Kernel 2: recurrence. 128 CTAs x 128 thr; warp = one batch row.
// Spike masks as 4 ballot words; s@W^T = ffs-walk over set bits, each bit one
// LDS.128 of a permuted weight column + two f32x2 adds.
// ---------------------------------------------------------------------------
__device__ __forceinline__ void accum_mask(
    const ulonglong2* __restrict__ W, const unsigned* m4, int lane,
    ull& h01, ull& h23)
{
#pragma unroll
    for (int q = 0; q < 4; ++q) {
        unsigned m = m4[q];
        while (m) {
            const int b = __ffs((int)m) - 1;
            m &= m - 1;
            const ulonglong2 v = W[((q << 5) + b) * 32 + lane];
            add2(h01, v.x);
            add2(h23, v.y);
        }
    }
}

__global__ void __launch_bounds__(128, 1) k2_rec(
    const float* __restrict__ Wh1, const float* __restrict__ Wi2,
    const float* __restrict__ bi2, const float* __restrict__ Wh2,
    const float* __restrict__ bh2, const float* __restrict__ Wo,
    const float* __restrict__ bo, float* __restrict__ out)
{
    extern __shared__ float sm[];
    float* wh1s = sm;              // each 16384 floats, permuted like k1's ws
    float* wi2s = sm + 16384;
    float* wh2s = sm + 32768;

    const int tid = threadIdx.x, lane = tid & 31, warp = tid >> 5;

    for (int i = tid; i < HD * HD; i += 128) {
        int j = i >> 7, k = i & 127;
        int d = k * 128 + ((j & 31) << 2) + (j >> 5);
        wh1s[d] = Wh1[i];
        wi2s[d] = Wi2[i];
        wh2s[d] = Wh2[i];
    }
    __syncthreads();

    const int row = blockIdx.x * 4 + warp;

    const ull b01 = pk2(bi2[lane]      + bh2[lane],      bi2[lane + 32] + bh2[lane + 32]);
    const ull b23 = pk2(bi2[lane + 64] + bh2[lane + 64], bi2[lane + 96] + bh2[lane + 96]);

    const ulonglong2* W1  = (const ulonglong2*)wh1s;
    const ulonglong2* W2i = (const ulonglong2*)wi2s;
    const ulonglong2* W2h = (const ulonglong2*)wh2s;

    const float4* pre = (const float4*)g_pre1 + (size_t)row * TS * 32 + lane;

    unsigned w1[4] = {0, 0, 0, 0};
    unsigned w2[4] = {0, 0, 0, 0};
    int c0 = 0, c1 = 0, c2 = 0, c3 = 0;

    float4 buf0 = pre[0];
    float4 buf1 = pre[32];

    for (int t = 0; t < TS; ++t) {
        const float4 cur = (t & 1) ? buf1 : buf0;
        if (t + 2 < TS) {
            const float4 nx = pre[(t + 2) * 32];
            if (t & 1) buf1 = nx; else buf0 = nx;
        }

        // layer 1: h1 = pre1 + s1 @ Wh1^T
        ull h01 = pk2(cur.x, cur.y), h23 = pk2(cur.z, cur.w);
        accum_mask(W1, w1, lane, h01, h23);

        const float2 ha = upk2(h01), hb = upk2(h23);
        w1[0] = __ballot_sync(0xffffffffu, ha.x >= 1.0f);
        w1[1] = __ballot_sync(0xffffffffu, ha.y >= 1.0f);
        w1[2] = __ballot_sync(0xffffffffu, hb.x >= 1.0f);
        w1[3] = __ballot_sync(0xffffffffu, hb.y >= 1.0f);

        // layer 2: h2 = bias2 + s1 @ Wi2^T + s2 @ Wh2^T
        ull g01 = b01, g23 = b23;
        accum_mask(W2i, w1, lane, g01, g23);
        accum_mask(W2h, w2, lane, g01, g23);

        const float2 ga = upk2(g01), gb = upk2(g23);
        const bool p0 = (ga.x >= 1.0f), p1 = (ga.y >= 1.0f);
        const bool p2 = (gb.x >= 1.0f), p3 = (gb.y >= 1.0f);
        w2[0] = __ballot_sync(0xffffffffu, p0);
        w2[1] = __ballot_sync(0xffffffffu, p1);
        w2[2] = __ballot_sync(0xffffffffu, p2);
        w2[3] = __ballot_sync(0xffffffffu, p3);
        c0 += p0; c1 += p1; c2 += p2; c3 += p3;
    }

    // epilogue: out[row] = bo + counts @ Wo^T / T
    const float f0 = (float)c0, f1 = (float)c1, f2 = (float)c2, f3 = (float)c3;
#pragma unroll
    for (int o = 0; o < DOUT; ++o) {
        const float* wr = Wo + o * HD;
        float p = f0 * wr[lane] + f1 * wr[lane + 32] + f2 * wr[lane + 64] + f3 * wr[lane + 96];
#pragma unroll
        for (int s = 16; s; s >>= 1) p += __shfl_xor_sync(0xffffffffu, p, s);
        if (lane == 0) out[row * DOUT + o] = bo[o] + p * (1.0f / (float)TS);
    }
}

extern "C" void kernel_launch(void* const* d_in, const int* in_sizes, int n_in,
                              void* d_out, int out_size)
{
    const float* x   = (const float*)d_in[0];
    const float* Wi1 = (const float*)d_in[1];
    const float* bi1 = (const float*)d_in[2];
    const float* Wh1 = (const float*)d_in[3];
    const float* bh1 = (const float*)d_in[4];
    const float* Wi2 = (const float*)d_in[5];
    const float* bi2 = (const float*)d_in[6];
    const float* Wh2 = (const float*)d_in[7];
    const float* bh2 = (const float*)d_in[8];
    const float* Wo  = (const float*)d_in[9];
    const float* bo  = (const float*)d_in[10];
    float* out = (float*)d_out;

    cudaFuncSetAttribute(k1_gemm, cudaFuncAttributeMaxDynamicSharedMemorySize, 98304);
    cudaFuncSetAttribute(k2_rec,  cudaFuncAttributeMaxDynamicSharedMemorySize, 196608);

    k1_gemm<<<MTOT / 64, 256, 98304>>>(x, Wi1, bi1, bh1);
    k2_rec<<<NB / 4, 128, 196608>>>(Wh1, Wi2, bi2, Wh2, bh2, Wo, bo, out);
}